// round 6
// baseline (speedup 1.0000x reference)
#include <cuda_runtime.h>
#include <cstdint>
#include <math.h>

#define BATCH   4096
#define NLEAF   50000
#define DIM     256
#define CHUNKL  5556
#define NCHUNK  9
#define NTILES  44
#define EPSF    1e-7f
#define SHORTL  16
#define NSLOT   8
#define NCANDR  (NCHUNK * NSLOT * 2)   // 144 per row

// smem: 2 stages of {Xhi,Xlo,Yhi,Ylo}, each 128 rows x 144B pitch (128B data)
#define PITCH    144
#define MATB     (128 * PITCH)         // 18432
#define STAGEB   (4 * MATB)            // 73728
#define OFF_SCL  (2 * STAGEB)          // 147456
#define DPITCH   132                   // dump pitch in floats (overlays stages)
#define SMEM_TOTAL (OFF_SCL + 3 * 128 * 4)  // 148992
#define INV254   0.003937007874015748f

__device__ float g_x2[BATCH];
__device__ float g_sx[BATCH];
__device__ float g_y2[NLEAF];
__device__ float g_sy[NLEAF];      // maxy/127
__device__ float g_invc[NLEAF];    // 1/(1-y2)
__device__ float g_y2inv[NLEAF];   // y2/(1-y2)
__device__ __align__(16) int8_t g_Xhi[(size_t)BATCH * DIM];
__device__ __align__(16) int8_t g_Xlo[(size_t)BATCH * DIM];
__device__ __align__(16) int8_t g_Yhi[(size_t)NLEAF * DIM];
__device__ __align__(16) int8_t g_Ylo[(size_t)NLEAF * DIM];
__device__ float g_cval[(size_t)NCHUNK * BATCH * NSLOT * 2];
__device__ int   g_cidx[(size_t)NCHUNK * BATCH * NSLOT * 2];

__device__ __forceinline__ uint32_t smem_to_u32(const void* p) {
    uint32_t a;
    asm("{ .reg .u64 t; cvta.to.shared.u64 t, %1; cvt.u32.u64 %0, t; }" : "=r"(a) : "l"(p));
    return a;
}
#define LDSM_X4(r, addr) \
    asm volatile("ldmatrix.sync.aligned.m8n8.x4.shared.b16 {%0,%1,%2,%3}, [%4];" \
        : "=r"((r)[0]), "=r"((r)[1]), "=r"((r)[2]), "=r"((r)[3]) : "r"(addr))
#define MMAS8(c, a, b0, b1) \
    asm volatile("mma.sync.aligned.m16n8k32.row.col.s32.s8.s8.s32 " \
        "{%0,%1,%2,%3},{%4,%5,%6,%7},{%8,%9},{%0,%1,%2,%3};" \
        : "+r"((c)[0]), "+r"((c)[1]), "+r"((c)[2]), "+r"((c)[3]) \
        : "r"((a)[0]), "r"((a)[1]), "r"((a)[2]), "r"((a)[3]), "r"(b0), "r"(b1))
#define CP_WAIT(n) asm volatile("cp.async.wait_group %0;" :: "n"(n) : "memory")

__device__ __forceinline__ int pack4(int a, int b, int c, int d) {
    return (a & 0xff) | ((b & 0xff) << 8) | ((c & 0xff) << 16) | ((d & 0xff) << 24);
}

// ---------------- Kernel 1: norms + 15-bit int8 split --------------------
// X rows: quantize x (scale Kx = 127/max|x|).  Y rows: quantize
// y'' = -2*inv*y (inv = 1/(1-y2)).  dot(x, y'') + x2*inv + y2*inv is the
// monotone hyperbolic ranking key; the affine part is added in the epilogue.
__global__ void prep_kernel(const float* __restrict__ X, const float* __restrict__ Y) {
    int warp = (blockIdx.x * blockDim.x + threadIdx.x) >> 5;
    int lane = threadIdx.x & 31;
    if (warp >= BATCH + NLEAF) return;
    bool isX = warp < BATCH;
    int row = isX ? warp : warp - BATCH;
    const float* src = (isX ? X : Y) + (size_t)row * DIM;
    float4 a = ((const float4*)src)[lane * 2];
    float4 b = ((const float4*)src)[lane * 2 + 1];
    float v[8] = {a.x, a.y, a.z, a.w, b.x, b.y, b.z, b.w};
    float s = 0.0f;
    #pragma unroll
    for (int i = 0; i < 8; i++) s += v[i] * v[i];
    #pragma unroll
    for (int o = 16; o; o >>= 1) s += __shfl_xor_sync(0xffffffffu, s, o);

    float w[8];
    float inv = 1.0f;
    if (isX) {
        #pragma unroll
        for (int i = 0; i < 8; i++) w[i] = v[i];
    } else {
        inv = 1.0f / (1.0f - s);
        float sc = -2.0f * inv;
        #pragma unroll
        for (int i = 0; i < 8; i++) w[i] = v[i] * sc;
    }
    float m = 0.0f;
    #pragma unroll
    for (int i = 0; i < 8; i++) m = fmaxf(m, fabsf(w[i]));
    #pragma unroll
    for (int o = 16; o; o >>= 1) m = fmaxf(m, __shfl_xor_sync(0xffffffffu, m, o));
    float K = 127.0f / m;

    int h[8], l[8];
    #pragma unroll
    for (int i = 0; i < 8; i++) {
        float sf = w[i] * K;
        float hf = rintf(sf);
        h[i] = (int)hf;
        l[i] = (int)rintf((sf - hf) * 254.0f);
    }
    int2 hp = make_int2(pack4(h[0], h[1], h[2], h[3]), pack4(h[4], h[5], h[6], h[7]));
    int2 lp = make_int2(pack4(l[0], l[1], l[2], l[3]), pack4(l[4], l[5], l[6], l[7]));
    if (isX) {
        ((int2*)(g_Xhi + (size_t)row * DIM))[lane] = hp;
        ((int2*)(g_Xlo + (size_t)row * DIM))[lane] = lp;
        if (lane == 0) { g_x2[row] = s; g_sx[row] = m * (1.0f / 127.0f); }
    } else {
        ((int2*)(g_Yhi + (size_t)row * DIM))[lane] = hp;
        ((int2*)(g_Ylo + (size_t)row * DIM))[lane] = lp;
        if (lane == 0) {
            g_y2[row] = s;
            g_sy[row] = m * (1.0f / 127.0f);
            g_invc[row] = inv;
            g_y2inv[row] = s * inv;
        }
    }
}

// cp.async one 128-byte k-chunk of all 4 matrices into one smem stage.
__device__ __forceinline__ void issue_loads(uint32_t stg, int tid, int mrow0,
                                            int leaf0, int kc) {
    const int k0 = kc * 128;
    #pragma unroll
    for (int i = 0; i < 16; i++) {
        int u = tid + 256 * i;
        int mat = u >> 10;
        int rem = u & 1023;
        int row = rem >> 3;
        int col = rem & 7;
        uint32_t dst = stg + (uint32_t)mat * MATB + (uint32_t)row * PITCH
                     + (uint32_t)col * 16;
        const int8_t* src;
        if (mat < 2) {
            src = (mat == 0 ? g_Xhi : g_Xlo) + (size_t)(mrow0 + row) * DIM + k0 + col * 16;
        } else {
            int leaf = leaf0 + row; if (leaf >= NLEAF) leaf = NLEAF - 1;
            src = (mat == 2 ? g_Yhi : g_Ylo) + (size_t)leaf * DIM + k0 + col * 16;
        }
        asm volatile("cp.async.cg.shared.global [%0], [%1], 16;"
                     :: "r"(dst), "l"(src) : "memory");
    }
    asm volatile("cp.async.commit_group;" ::: "memory");
}

// ---------------- Kernel 2: int8x3 mma.sync GEMM + fused exact top-8 -----
// 256 threads = 8 warps (2m x 4n), warp tile 64x32, block tile 128x128, K=256.
// Passes: HH (hi*hi) and CR (hi*lo + lo*hi, shared s32 accumulator).
// dot = (HH + CR/254) * sx[row] * sy[col];  key = dot + x2*inv[col] + y2inv[col].
__global__ void __launch_bounds__(256, 1) main_kernel() {
    extern __shared__ char smem[];
    const uint32_t sb = smem_to_u32(smem);
    const int tid = threadIdx.x, lane = tid & 31, w = tid >> 5;
    const int wm = w >> 2, wn = w & 3;
    const int mblk = blockIdx.x, chunk = blockIdx.y;
    const int mrow0 = mblk * 128;
    const int leaf_base = chunk * CHUNKL;
    int leaf_end = leaf_base + CHUNKL; if (leaf_end > NLEAF) leaf_end = NLEAF;

    // scan-thread row constants
    const int grow_s = mrow0 + (tid & 127);
    const int half = tid >> 7;
    const float x2r = g_x2[grow_s];
    const float sxr = g_sx[grow_s];

    // ldmatrix lane address components
    const uint32_t aoff = (uint32_t)(lane & 15) * PITCH + ((lane >> 4) & 1) * 16;
    const uint32_t boff = (uint32_t)((lane & 7) + ((lane >> 4) & 1) * 8) * PITCH
                        + ((lane >> 3) & 1) * 16;

    const uint32_t sY  = sb + OFF_SCL;
    const uint32_t sIC = sb + OFF_SCL + 512;
    const uint32_t sY2 = sb + OFF_SCL + 1024;

    float tv[NSLOT]; int ti[NSLOT];
    #pragma unroll
    for (int q = 0; q < NSLOT; q++) { tv[q] = INFINITY; ti[q] = -1; }

    for (int t = 0; t < NTILES; t++) {
        const int leaf0 = leaf_base + t * 128;
        issue_loads(sb, tid, mrow0, leaf0, 0);

        int HH[4][4][4], CR[4][4][4];
        #pragma unroll
        for (int mi = 0; mi < 4; mi++)
            #pragma unroll
            for (int ni = 0; ni < 4; ni++)
                #pragma unroll
                for (int e = 0; e < 4; e++) { HH[mi][ni][e] = 0; CR[mi][ni][e] = 0; }

        #pragma unroll
        for (int kc = 0; kc < 2; kc++) {
            const uint32_t stg = sb + (uint32_t)kc * STAGEB;
            if (kc == 0) {
                issue_loads(sb + STAGEB, tid, mrow0, leaf0, 1);
                CP_WAIT(1);
            } else {
                CP_WAIT(0);
            }
            __syncthreads();

            #pragma unroll
            for (int ks = 0; ks < 4; ks++) {
                uint32_t Ah[4][4], Al[4][4], Bh[2][4], Bl[2][4];
                #pragma unroll
                for (int mi = 0; mi < 4; mi++) {
                    uint32_t r = (uint32_t)(wm * 64 + mi * 16) * PITCH + ks * 32;
                    LDSM_X4(Ah[mi], stg + r + aoff);
                    LDSM_X4(Al[mi], stg + MATB + r + aoff);
                }
                #pragma unroll
                for (int nb = 0; nb < 2; nb++) {
                    uint32_t r = (uint32_t)(wn * 32 + nb * 16) * PITCH + ks * 32;
                    LDSM_X4(Bh[nb], stg + 2 * MATB + r + boff);
                    LDSM_X4(Bl[nb], stg + 3 * MATB + r + boff);
                }
                #pragma unroll
                for (int mi = 0; mi < 4; mi++) {
                    #pragma unroll
                    for (int nb = 0; nb < 2; nb++) {
                        MMAS8(HH[mi][2 * nb],     Ah[mi], Bh[nb][0], Bh[nb][1]);
                        MMAS8(HH[mi][2 * nb + 1], Ah[mi], Bh[nb][2], Bh[nb][3]);
                        MMAS8(CR[mi][2 * nb],     Ah[mi], Bl[nb][0], Bl[nb][1]);
                        MMAS8(CR[mi][2 * nb + 1], Ah[mi], Bl[nb][2], Bl[nb][3]);
                        MMAS8(CR[mi][2 * nb],     Al[mi], Bh[nb][0], Bh[nb][1]);
                        MMAS8(CR[mi][2 * nb + 1], Al[mi], Bh[nb][2], Bh[nb][3]);
                    }
                }
            }
        }

        // combine (HH + CR/254) and dump f32 into smem (overlays dead stage 0)
        {
            const int r0 = wm * 64 + (lane >> 2);
            const int c0 = wn * 32 + 2 * (lane & 3);
            #pragma unroll
            for (int mi = 0; mi < 4; mi++) {
                #pragma unroll
                for (int ni = 0; ni < 4; ni++) {
                    float d0 = fmaf((float)CR[mi][ni][0], INV254, (float)HH[mi][ni][0]);
                    float d1 = fmaf((float)CR[mi][ni][1], INV254, (float)HH[mi][ni][1]);
                    float d2 = fmaf((float)CR[mi][ni][2], INV254, (float)HH[mi][ni][2]);
                    float d3 = fmaf((float)CR[mi][ni][3], INV254, (float)HH[mi][ni][3]);
                    uint32_t a0 = sb + (uint32_t)((r0 + mi * 16) * DPITCH + c0 + ni * 8) * 4;
                    asm volatile("st.shared.v2.f32 [%0], {%1,%2};"
                                 :: "r"(a0), "f"(d0), "f"(d1) : "memory");
                    asm volatile("st.shared.v2.f32 [%0], {%1,%2};"
                                 :: "r"(a0 + 8 * DPITCH * 4), "f"(d2), "f"(d3) : "memory");
                }
            }
        }
        // per-leaf scales for this tile -> smem
        if (tid < 128) {
            int leaf = leaf0 + tid; if (leaf >= NLEAF) leaf = NLEAF - 1;
            float vy = g_sy[leaf], vi = g_invc[leaf], v2 = g_y2inv[leaf];
            asm volatile("st.shared.f32 [%0], %1;" :: "r"(sY  + tid * 4), "f"(vy) : "memory");
            asm volatile("st.shared.f32 [%0], %1;" :: "r"(sIC + tid * 4), "f"(vi) : "memory");
            asm volatile("st.shared.f32 [%0], %1;" :: "r"(sY2 + tid * 4), "f"(v2) : "memory");
        }
        __syncthreads();

        // scan: thread owns (row = tid&127, half): exact top-8 over 64 cols
        {
            int nvalid = leaf_end - leaf0; if (nvalid > 128) nvalid = 128;
            const uint32_t rb = sb + (uint32_t)(tid & 127) * (DPITCH * 4) + half * 256;
            #pragma unroll 4
            for (int j4 = 0; j4 < 16; j4++) {
                float v0, v1, v2, v3;
                asm volatile("ld.shared.v4.f32 {%0,%1,%2,%3}, [%4];"
                             : "=f"(v0), "=f"(v1), "=f"(v2), "=f"(v3)
                             : "r"(rb + j4 * 16));
                float vv[4] = {v0, v1, v2, v3};
                #pragma unroll
                for (int e = 0; e < 4; e++) {
                    int col = half * 64 + j4 * 4 + e;
                    float syc, icc, y2c;
                    asm volatile("ld.shared.f32 %0, [%1];" : "=f"(syc) : "r"(sY  + col * 4));
                    asm volatile("ld.shared.f32 %0, [%1];" : "=f"(icc) : "r"(sIC + col * 4));
                    asm volatile("ld.shared.f32 %0, [%1];" : "=f"(y2c) : "r"(sY2 + col * 4));
                    float key = fmaxf(fmaf(vv[e] * sxr, syc, fmaf(x2r, icc, y2c)), 0.0f);
                    if (col < nvalid && key < tv[NSLOT - 1]) {
                        tv[NSLOT - 1] = key; ti[NSLOT - 1] = leaf0 + col;
                        #pragma unroll
                        for (int q = NSLOT - 1; q > 0; q--) {
                            if (tv[q] < tv[q - 1]) {
                                float fv = tv[q]; tv[q] = tv[q - 1]; tv[q - 1] = fv;
                                int iv = ti[q]; ti[q] = ti[q - 1]; ti[q - 1] = iv;
                            }
                        }
                    }
                }
            }
        }
        __syncthreads();
    }

    const size_t cb = (((size_t)chunk * BATCH + grow_s) * 2 + half) * NSLOT;
    #pragma unroll
    for (int q = 0; q < NSLOT; q++) { g_cval[cb + q] = tv[q]; g_cidx[cb + q] = ti[q]; }
}

// ---------------- Kernel 3: merge 144 cands -> top-16, exact re-rank ------
__global__ void merge_kernel(const float* __restrict__ X, const float* __restrict__ Y,
                             const int* __restrict__ ids, const float* __restrict__ thr_p,
                             float* __restrict__ out, int out_size) {
    const int lane = threadIdx.x & 31;
    const int row = blockIdx.x * 8 + (threadIdx.x >> 5);
    if (row >= BATCH) return;
    const unsigned FULL = 0xffffffffu;

    float lv[SHORTL]; int li[SHORTL];
    #pragma unroll
    for (int s = 0; s < SHORTL; s++) { lv[s] = INFINITY; li[s] = 0x7fffffff; }
    for (int f = lane; f < NCANDR; f += 32) {
        int ch = f >> 4, r = f & 15;
        size_t a = ((size_t)ch * BATCH + row) * 16 + r;
        float v = g_cval[a];
        if (v < lv[SHORTL - 1]) {
            int ix = g_cidx[a];
            if (ix < 0) continue;
            int p = SHORTL - 1;
            while (p > 0 && (lv[p-1] > v || (lv[p-1] == v && li[p-1] > ix))) {
                lv[p] = lv[p-1]; li[p] = li[p-1]; p--;
            }
            lv[p] = v; li[p] = ix;
        }
    }

    int head = 0, seli = -1;
    for (int r = 0; r < SHORTL; r++) {
        float bv = (head < SHORTL) ? lv[head] : INFINITY;
        int   bi = (head < SHORTL) ? li[head] : 0x7fffffff;
        int   bl = lane;
        #pragma unroll
        for (int o = 16; o > 0; o >>= 1) {
            float ov = __shfl_down_sync(FULL, bv, o);
            int oi = __shfl_down_sync(FULL, bi, o);
            int ol = __shfl_down_sync(FULL, bl, o);
            if (ov < bv || (ov == bv && oi < bi)) { bv = ov; bi = oi; bl = ol; }
        }
        bi = __shfl_sync(FULL, bi, 0);
        bl = __shfl_sync(FULL, bl, 0);
        if (lane == r) seli = bi;
        if (lane == bl) head++;
    }

    float x2 = g_x2[row];
    const float4* xr = (const float4*)(X + (size_t)row * DIM);
    float4 xa = xr[lane * 2], xb = xr[lane * 2 + 1];
    float my_dist = INFINITY;
    for (int cc = 0; cc < SHORTL; cc++) {
        int ci = __shfl_sync(FULL, seli, cc);
        float dist = INFINITY;
        if (ci >= 0 && ci < NLEAF) {
            const float4* yr = (const float4*)(Y + (size_t)ci * DIM);
            float4 ya = yr[lane * 2], yb = yr[lane * 2 + 1];
            float s = xa.x*ya.x + xa.y*ya.y + xa.z*ya.z + xa.w*ya.w
                    + xb.x*yb.x + xb.y*yb.y + xb.z*yb.z + xb.w*yb.w;
            #pragma unroll
            for (int o = 16; o > 0; o >>= 1) s += __shfl_down_sync(FULL, s, o);
            s = __shfl_sync(FULL, s, 0);
            float y2 = g_y2[ci];
            float sq    = fmaxf(x2 + y2 - 2.0f * s, 0.0f);
            float denom = fmaxf((1.0f - x2) * (1.0f - y2), EPSF);
            float arg   = fmaxf(1.0f + 2.0f * sq / denom, 1.0f + EPSF);
            dist = acoshf(arg);
        } else ci = -1;
        if (lane == cc) { my_dist = dist; seli = ci; }
    }

    float dall[SHORTL]; int iall[SHORTL];
    for (int cc = 0; cc < SHORTL; cc++) {
        dall[cc] = __shfl_sync(FULL, my_dist, cc);
        iall[cc] = __shfl_sync(FULL, seli, cc);
    }
    for (int a2 = 1; a2 < SHORTL; a2++) {
        float dv = dall[a2]; int iv = iall[a2];
        int p = a2;
        while (p > 0 && (dall[p-1] > dv || (dall[p-1] == dv && iall[p-1] > iv))) {
            dall[p] = dall[p-1]; iall[p] = iall[p-1]; p--;
        }
        dall[p] = dv; iall[p] = iv;
    }

    if (lane == 0) {
        float score = dall[0];
        out[row] = score;
        if (out_size >= 2 * BATCH)
            out[BATCH + row] = (score > thr_p[0]) ? 1.0f : 0.0f;
        if (out_size >= 7 * BATCH) {
            #pragma unroll
            for (int j = 0; j < 5; j++) {
                int ci = iall[j];
                out[2 * BATCH + (size_t)row * 5 + j] = (float)((ci >= 0) ? ids[ci] : 0);
            }
        }
    }
}

// ---------------------------------------------------------------------------
extern "C" void kernel_launch(void* const* d_in, const int* in_sizes, int n_in,
                              void* d_out, int out_size) {
    const float* X   = (const float*)d_in[0];
    const float* Y   = (const float*)d_in[1];
    const int*   ids = (const int*)d_in[2];
    const float* thr = (const float*)d_in[3];
    float* out = (float*)d_out;

    cudaFuncSetAttribute(main_kernel, cudaFuncAttributeMaxDynamicSharedMemorySize,
                         SMEM_TOTAL);

    int prep_warps = BATCH + NLEAF;
    prep_kernel<<<(prep_warps + 7) / 8, 256>>>(X, Y);

    main_kernel<<<dim3(BATCH / 128, NCHUNK), 256, SMEM_TOTAL>>>();

    merge_kernel<<<BATCH / 8, 256>>>(X, Y, ids, thr, out, out_size);
}

// round 7
// speedup vs baseline: 4.7011x; 4.7011x over previous
#include <cuda_runtime.h>
#include <cuda_bf16.h>
#include <cstdint>
#include <math.h>

#define BATCH   4096
#define NLEAF   50000
#define DIM     256
#define CHUNKL  5556
#define NCHUNK  9
#define NTILES  44
#define EPSF    1e-7f
#define SHORTL  16
#define NSLOT   8
#define NCANDR  (NCHUNK * NSLOT * 2)   // 144 per row

// smem: 2 stages of {Xbf, Ybf}, each mat 128 rows x 144B pitch (64 bf16 = 128B data)
#define PITCH    144
#define MATB     (128 * PITCH)         // 18432
#define STAGEB   (2 * MATB)            // 36864
#define OFF_SCL  (2 * STAGEB)          // 73728 (after both stages)
#define DPITCH   132                   // dump pitch in floats (overlays stages)
#define SMEM_TOTAL (OFF_SCL + 2 * 128 * 4)  // 74752

__device__ float g_x2[BATCH];
__device__ float g_y2[NLEAF];
__device__ float g_invc[NLEAF];    // 1/(1-y2)
__device__ float g_y2inv[NLEAF];   // y2/(1-y2)
__device__ __align__(16) __nv_bfloat16 g_Xb[(size_t)BATCH * DIM];
__device__ __align__(16) __nv_bfloat16 g_Yb[(size_t)NLEAF * DIM];   // -2*inv*y in bf16
__device__ float g_cval[(size_t)NCHUNK * BATCH * NSLOT * 2];
__device__ int   g_cidx[(size_t)NCHUNK * BATCH * NSLOT * 2];

__device__ __forceinline__ uint32_t smem_to_u32(const void* p) {
    uint32_t a;
    asm("{ .reg .u64 t; cvta.to.shared.u64 t, %1; cvt.u32.u64 %0, t; }" : "=r"(a) : "l"(p));
    return a;
}
#define LDSM_X4(r, addr) \
    asm volatile("ldmatrix.sync.aligned.m8n8.x4.shared.b16 {%0,%1,%2,%3}, [%4];" \
        : "=r"((r)[0]), "=r"((r)[1]), "=r"((r)[2]), "=r"((r)[3]) : "r"(addr))
#define MMA16816(c, a, b0, b1) \
    asm volatile("mma.sync.aligned.m16n8k16.row.col.f32.bf16.bf16.f32 " \
        "{%0,%1,%2,%3},{%4,%5,%6,%7},{%8,%9},{%0,%1,%2,%3};" \
        : "+f"((c)[0]), "+f"((c)[1]), "+f"((c)[2]), "+f"((c)[3]) \
        : "r"((a)[0]), "r"((a)[1]), "r"((a)[2]), "r"((a)[3]), "r"(b0), "r"(b1))
#define CP_WAIT(n) asm volatile("cp.async.wait_group %0;" :: "n"(n) : "memory")

__device__ __forceinline__ unsigned bfu(__nv_bfloat16 h) {
    return (unsigned)__bfloat16_as_ushort(h);
}

// ---------------- Kernel 1: norms + single bf16 quantization --------------
// X rows: bf16(x).  Y rows: bf16(-2*inv*y), inv = 1/(1-y2).
// key = dot + x2*inv[col] + y2inv[col] (affine part added in the epilogue)
// is monotone in the hyperbolic distance per row. Single-pass bf16 error
// (~1e-3 worst) << top-16 shortlist safety gap; exact fp32 re-rank follows.
__global__ void prep_kernel(const float* __restrict__ X, const float* __restrict__ Y) {
    int warp = (blockIdx.x * blockDim.x + threadIdx.x) >> 5;
    int lane = threadIdx.x & 31;
    if (warp >= BATCH + NLEAF) return;
    bool isX = warp < BATCH;
    int row = isX ? warp : warp - BATCH;
    const float* src = (isX ? X : Y) + (size_t)row * DIM;
    float4 a = ((const float4*)src)[lane * 2];
    float4 b = ((const float4*)src)[lane * 2 + 1];
    float v[8] = {a.x, a.y, a.z, a.w, b.x, b.y, b.z, b.w};
    float s = 0.0f;
    #pragma unroll
    for (int i = 0; i < 8; i++) s += v[i] * v[i];
    #pragma unroll
    for (int o = 16; o; o >>= 1) s += __shfl_xor_sync(0xffffffffu, s, o);

    float sc = 1.0f;
    __nv_bfloat16* dst;
    if (isX) {
        if (lane == 0) g_x2[row] = s;
        dst = g_Xb + (size_t)row * DIM;
    } else {
        float inv = 1.0f / (1.0f - s);
        if (lane == 0) {
            g_y2[row] = s;
            g_invc[row] = inv;
            g_y2inv[row] = s * inv;
        }
        sc = -2.0f * inv;
        dst = g_Yb + (size_t)row * DIM;
    }
    unsigned w[4];
    #pragma unroll
    for (int i = 0; i < 4; i++) {
        __nv_bfloat16 h0 = __float2bfloat16(v[2*i] * sc);
        __nv_bfloat16 h1 = __float2bfloat16(v[2*i+1] * sc);
        w[i] = bfu(h0) | (bfu(h1) << 16);
    }
    ((uint4*)dst)[lane] = make_uint4(w[0], w[1], w[2], w[3]);
}

// cp.async one 64-element (128B) k-chunk of X and Y tiles into one smem stage.
// 2 mats x 128 rows x 8 cols(16B) = 2048 transfers / 256 threads = 8 each.
__device__ __forceinline__ void issue_loads(uint32_t stg, int tid, int mrow0,
                                            int leaf0, int kc) {
    const int k0 = kc * 64;
    #pragma unroll
    for (int i = 0; i < 8; i++) {
        int u = tid + 256 * i;
        int mat = u >> 10;
        int rem = u & 1023;
        int row = rem >> 3;
        int col = rem & 7;
        uint32_t dst = stg + (uint32_t)mat * MATB + (uint32_t)row * PITCH
                     + (uint32_t)col * 16;
        const __nv_bfloat16* src;
        if (mat == 0) {
            src = g_Xb + (size_t)(mrow0 + row) * DIM + k0 + col * 8;
        } else {
            int leaf = leaf0 + row; if (leaf >= NLEAF) leaf = NLEAF - 1;
            src = g_Yb + (size_t)leaf * DIM + k0 + col * 8;
        }
        asm volatile("cp.async.cg.shared.global [%0], [%1], 16;"
                     :: "r"(dst), "l"(src) : "memory");
    }
    asm volatile("cp.async.commit_group;" ::: "memory");
}

// ---------------- Kernel 2: single-pass bf16 mma.sync GEMM + fused top-8 --
// 256 threads = 8 warps (2m x 4n), warp tile 64x32, block tile 128x128, K=256.
__global__ void __launch_bounds__(256, 2) main_kernel() {
    extern __shared__ char smem[];
    const uint32_t sb = smem_to_u32(smem);
    const int tid = threadIdx.x, lane = tid & 31, w = tid >> 5;
    const int wm = w >> 2, wn = w & 3;
    const int mblk = blockIdx.x, chunk = blockIdx.y;
    const int mrow0 = mblk * 128;
    const int leaf_base = chunk * CHUNKL;
    int leaf_end = leaf_base + CHUNKL; if (leaf_end > NLEAF) leaf_end = NLEAF;

    // scan-thread row constants
    const int grow_s = mrow0 + (tid & 127);
    const int half = tid >> 7;
    const float x2r = g_x2[grow_s];

    // ldmatrix lane address components
    const uint32_t aoff = (uint32_t)(wm * 64 + (lane & 15)) * PITCH
                        + ((lane >> 4) & 1) * 16;
    const uint32_t boff = (uint32_t)(wn * 32 + (lane & 7) + ((lane >> 4) & 1) * 8) * PITCH
                        + ((lane >> 3) & 1) * 16;

    const uint32_t sIC = sb + OFF_SCL;
    const uint32_t sY2 = sb + OFF_SCL + 512;

    float tv[NSLOT]; int ti[NSLOT];
    #pragma unroll
    for (int q = 0; q < NSLOT; q++) { tv[q] = INFINITY; ti[q] = -1; }

    for (int t = 0; t < NTILES; t++) {
        const int leaf0 = leaf_base + t * 128;
        issue_loads(sb, tid, mrow0, leaf0, 0);

        float c[4][4][4];
        #pragma unroll
        for (int mi = 0; mi < 4; mi++)
            #pragma unroll
            for (int ni = 0; ni < 4; ni++)
                #pragma unroll
                for (int e = 0; e < 4; e++) c[mi][ni][e] = 0.0f;

        #pragma unroll
        for (int kc = 0; kc < 4; kc++) {
            const uint32_t stg = sb + (uint32_t)(kc & 1) * STAGEB;
            if (kc < 3) {
                issue_loads(sb + (uint32_t)((kc + 1) & 1) * STAGEB, tid, mrow0, leaf0, kc + 1);
                CP_WAIT(1);
            } else {
                CP_WAIT(0);
            }
            __syncthreads();

            #pragma unroll
            for (int ks = 0; ks < 4; ks++) {
                uint32_t a[4][4], b[2][4];
                #pragma unroll
                for (int mi = 0; mi < 4; mi++)
                    LDSM_X4(a[mi], stg + (uint32_t)(mi * 16) * PITCH + ks * 32 + aoff);
                #pragma unroll
                for (int nb = 0; nb < 2; nb++)
                    LDSM_X4(b[nb], stg + MATB + (uint32_t)(nb * 16) * PITCH + ks * 32 + boff);
                #pragma unroll
                for (int mi = 0; mi < 4; mi++) {
                    #pragma unroll
                    for (int nb = 0; nb < 2; nb++) {
                        MMA16816(c[mi][2 * nb],     a[mi], b[nb][0], b[nb][1]);
                        MMA16816(c[mi][2 * nb + 1], a[mi], b[nb][2], b[nb][3]);
                    }
                }
            }
            __syncthreads();
        }

        // dump accum (128x128 f32) into smem (overlays dead stage buffers)
        {
            const int r0 = wm * 64 + (lane >> 2);
            const int c0 = wn * 32 + 2 * (lane & 3);
            #pragma unroll
            for (int mi = 0; mi < 4; mi++) {
                #pragma unroll
                for (int ni = 0; ni < 4; ni++) {
                    uint32_t a0 = sb + (uint32_t)((r0 + mi * 16) * DPITCH + c0 + ni * 8) * 4;
                    asm volatile("st.shared.v2.f32 [%0], {%1,%2};"
                                 :: "r"(a0), "f"(c[mi][ni][0]), "f"(c[mi][ni][1]) : "memory");
                    asm volatile("st.shared.v2.f32 [%0], {%1,%2};"
                                 :: "r"(a0 + 8 * DPITCH * 4), "f"(c[mi][ni][2]), "f"(c[mi][ni][3]) : "memory");
                }
            }
        }
        // per-leaf affine terms for this tile -> smem
        if (tid < 128) {
            int leaf = leaf0 + tid; if (leaf >= NLEAF) leaf = NLEAF - 1;
            float vi = g_invc[leaf], v2 = g_y2inv[leaf];
            asm volatile("st.shared.f32 [%0], %1;" :: "r"(sIC + tid * 4), "f"(vi) : "memory");
            asm volatile("st.shared.f32 [%0], %1;" :: "r"(sY2 + tid * 4), "f"(v2) : "memory");
        }
        __syncthreads();

        // scan: thread owns (row = tid&127, half): exact top-8 over 64 cols
        {
            int nvalid = leaf_end - leaf0; if (nvalid > 128) nvalid = 128;
            const uint32_t rb = sb + (uint32_t)(tid & 127) * (DPITCH * 4) + half * 256;
            #pragma unroll 4
            for (int j4 = 0; j4 < 16; j4++) {
                float v0, v1, v2, v3;
                asm volatile("ld.shared.v4.f32 {%0,%1,%2,%3}, [%4];"
                             : "=f"(v0), "=f"(v1), "=f"(v2), "=f"(v3)
                             : "r"(rb + j4 * 16));
                float vv[4] = {v0, v1, v2, v3};
                #pragma unroll
                for (int e = 0; e < 4; e++) {
                    int col = half * 64 + j4 * 4 + e;
                    float icc, y2c;
                    asm volatile("ld.shared.f32 %0, [%1];" : "=f"(icc) : "r"(sIC + col * 4));
                    asm volatile("ld.shared.f32 %0, [%1];" : "=f"(y2c) : "r"(sY2 + col * 4));
                    float key = fmaxf(fmaf(x2r, icc, y2c) + vv[e], 0.0f);
                    if (col < nvalid && key < tv[NSLOT - 1]) {
                        tv[NSLOT - 1] = key; ti[NSLOT - 1] = leaf0 + col;
                        #pragma unroll
                        for (int q = NSLOT - 1; q > 0; q--) {
                            if (tv[q] < tv[q - 1]) {
                                float fv = tv[q]; tv[q] = tv[q - 1]; tv[q - 1] = fv;
                                int iv = ti[q]; ti[q] = ti[q - 1]; ti[q - 1] = iv;
                            }
                        }
                    }
                }
            }
        }
        __syncthreads();
    }

    const size_t cb = (((size_t)chunk * BATCH + grow_s) * 2 + half) * NSLOT;
    #pragma unroll
    for (int q = 0; q < NSLOT; q++) { g_cval[cb + q] = tv[q]; g_cidx[cb + q] = ti[q]; }
}

// ---------------- Kernel 3: merge 144 cands -> top-16, exact re-rank ------
__global__ void merge_kernel(const float* __restrict__ X, const float* __restrict__ Y,
                             const int* __restrict__ ids, const float* __restrict__ thr_p,
                             float* __restrict__ out, int out_size) {
    const int lane = threadIdx.x & 31;
    const int row = blockIdx.x * 8 + (threadIdx.x >> 5);
    if (row >= BATCH) return;
    const unsigned FULL = 0xffffffffu;

    float lv[SHORTL]; int li[SHORTL];
    #pragma unroll
    for (int s = 0; s < SHORTL; s++) { lv[s] = INFINITY; li[s] = 0x7fffffff; }
    for (int f = lane; f < NCANDR; f += 32) {
        int ch = f >> 4, r = f & 15;
        size_t a = ((size_t)ch * BATCH + row) * 16 + r;
        float v = g_cval[a];
        if (v < lv[SHORTL - 1]) {
            int ix = g_cidx[a];
            if (ix < 0) continue;
            int p = SHORTL - 1;
            while (p > 0 && (lv[p-1] > v || (lv[p-1] == v && li[p-1] > ix))) {
                lv[p] = lv[p-1]; li[p] = li[p-1]; p--;
            }
            lv[p] = v; li[p] = ix;
        }
    }

    int head = 0, seli = -1;
    for (int r = 0; r < SHORTL; r++) {
        float bv = (head < SHORTL) ? lv[head] : INFINITY;
        int   bi = (head < SHORTL) ? li[head] : 0x7fffffff;
        int   bl = lane;
        #pragma unroll
        for (int o = 16; o > 0; o >>= 1) {
            float ov = __shfl_down_sync(FULL, bv, o);
            int oi = __shfl_down_sync(FULL, bi, o);
            int ol = __shfl_down_sync(FULL, bl, o);
            if (ov < bv || (ov == bv && oi < bi)) { bv = ov; bi = oi; bl = ol; }
        }
        bi = __shfl_sync(FULL, bi, 0);
        bl = __shfl_sync(FULL, bl, 0);
        if (lane == r) seli = bi;
        if (lane == bl) head++;
    }

    float x2 = g_x2[row];
    const float4* xr = (const float4*)(X + (size_t)row * DIM);
    float4 xa = xr[lane * 2], xb = xr[lane * 2 + 1];
    float my_dist = INFINITY;
    for (int cc = 0; cc < SHORTL; cc++) {
        int ci = __shfl_sync(FULL, seli, cc);
        float dist = INFINITY;
        if (ci >= 0 && ci < NLEAF) {
            const float4* yr = (const float4*)(Y + (size_t)ci * DIM);
            float4 ya = yr[lane * 2], yb = yr[lane * 2 + 1];
            float s = xa.x*ya.x + xa.y*ya.y + xa.z*ya.z + xa.w*ya.w
                    + xb.x*yb.x + xb.y*yb.y + xb.z*yb.z + xb.w*yb.w;
            #pragma unroll
            for (int o = 16; o > 0; o >>= 1) s += __shfl_down_sync(FULL, s, o);
            s = __shfl_sync(FULL, s, 0);
            float y2 = g_y2[ci];
            float sq    = fmaxf(x2 + y2 - 2.0f * s, 0.0f);
            float denom = fmaxf((1.0f - x2) * (1.0f - y2), EPSF);
            float arg   = fmaxf(1.0f + 2.0f * sq / denom, 1.0f + EPSF);
            dist = acoshf(arg);
        } else ci = -1;
        if (lane == cc) { my_dist = dist; seli = ci; }
    }

    float dall[SHORTL]; int iall[SHORTL];
    for (int cc = 0; cc < SHORTL; cc++) {
        dall[cc] = __shfl_sync(FULL, my_dist, cc);
        iall[cc] = __shfl_sync(FULL, seli, cc);
    }
    for (int a2 = 1; a2 < SHORTL; a2++) {
        float dv = dall[a2]; int iv = iall[a2];
        int p = a2;
        while (p > 0 && (dall[p-1] > dv || (dall[p-1] == dv && iall[p-1] > iv))) {
            dall[p] = dall[p-1]; iall[p] = iall[p-1]; p--;
        }
        dall[p] = dv; iall[p] = iv;
    }

    if (lane == 0) {
        float score = dall[0];
        out[row] = score;
        if (out_size >= 2 * BATCH)
            out[BATCH + row] = (score > thr_p[0]) ? 1.0f : 0.0f;
        if (out_size >= 7 * BATCH) {
            #pragma unroll
            for (int j = 0; j < 5; j++) {
                int ci = iall[j];
                out[2 * BATCH + (size_t)row * 5 + j] = (float)((ci >= 0) ? ids[ci] : 0);
            }
        }
    }
}

// ---------------------------------------------------------------------------
extern "C" void kernel_launch(void* const* d_in, const int* in_sizes, int n_in,
                              void* d_out, int out_size) {
    const float* X   = (const float*)d_in[0];
    const float* Y   = (const float*)d_in[1];
    const int*   ids = (const int*)d_in[2];
    const float* thr = (const float*)d_in[3];
    float* out = (float*)d_out;

    cudaFuncSetAttribute(main_kernel, cudaFuncAttributeMaxDynamicSharedMemorySize,
                         SMEM_TOTAL);

    int prep_warps = BATCH + NLEAF;
    prep_kernel<<<(prep_warps + 7) / 8, 256>>>(X, Y);

    main_kernel<<<dim3(BATCH / 128, NCHUNK), 256, SMEM_TOTAL>>>();

    merge_kernel<<<BATCH / 8, 256>>>(X, Y, ids, thr, out, out_size);
}